// round 2
// baseline (speedup 1.0000x reference)
#include <cuda_runtime.h>
#include <cuda_bf16.h>

// Problem constants
#define BB   4
#define SS   2048
#define EE   1024
#define HH   16
#define DD   64
#define MM   (BB * SS)          // 8192 rows for projections

// Scratch (device globals: allocation-free per harness rules)
__device__ float g_q[BB * HH * SS * DD];   // [B,H,S,D]
__device__ float g_k[BB * HH * SS * DD];
__device__ float g_v[BB * HH * SS * DD];
__device__ float g_ctx[MM * EE];           // [B,S,E]

// ---------------------------------------------------------------------------
// Projection GEMM: out[m,n] = sum_k A[m,k] * W[n,k]   (x @ W^T)
// A: [M=8192, K=1024] row-major, W: [N=1024, K=1024] row-major.
// BM=BN=128, BK=16, 256 threads, 8x8 per thread.
// scatter=1: write to [B,H,S,D] layout (q/k/v). scatter=0: write [m, n] row-major.
// ---------------------------------------------------------------------------
__global__ __launch_bounds__(256) void proj_gemm(
    const float* __restrict__ A,
    const float* __restrict__ W,
    float* __restrict__ out,
    int scatter)
{
    const int K = EE;
    __shared__ float As[16][128];   // As[k][m] (transposed for coalesced compute reads)
    __shared__ float Bs[16][128];   // Bs[k][n]

    const int tid = threadIdx.x;
    const int m0 = blockIdx.y * 128;
    const int n0 = blockIdx.x * 128;
    const int ty = tid >> 4;        // 0..15
    const int tx = tid & 15;        // 0..15

    const float* Ap = A + m0 * K;
    const float* Wp = W + n0 * K;

    float acc[8][8];
#pragma unroll
    for (int i = 0; i < 8; ++i)
#pragma unroll
        for (int j = 0; j < 8; ++j) acc[i][j] = 0.0f;

    for (int k0 = 0; k0 < K; k0 += 16) {
        // Cooperative load of 128x16 tiles of A and W, stored transposed.
#pragma unroll
        for (int l = 0; l < 2; ++l) {
            int i  = tid + l * 256;      // 0..511
            int r  = i >> 2;             // 0..127
            int cg = (i & 3) * 4;        // 0,4,8,12
            float4 va = *(const float4*)(Ap + r * K + k0 + cg);
            As[cg + 0][r] = va.x; As[cg + 1][r] = va.y;
            As[cg + 2][r] = va.z; As[cg + 3][r] = va.w;
            float4 vb = *(const float4*)(Wp + r * K + k0 + cg);
            Bs[cg + 0][r] = vb.x; Bs[cg + 1][r] = vb.y;
            Bs[cg + 2][r] = vb.z; Bs[cg + 3][r] = vb.w;
        }
        __syncthreads();

#pragma unroll
        for (int k = 0; k < 16; ++k) {
            float a[8], b[8];
            *(float4*)&a[0] = *(const float4*)&As[k][ty * 8];
            *(float4*)&a[4] = *(const float4*)&As[k][ty * 8 + 4];
            *(float4*)&b[0] = *(const float4*)&Bs[k][tx * 8];
            *(float4*)&b[4] = *(const float4*)&Bs[k][tx * 8 + 4];
#pragma unroll
            for (int i = 0; i < 8; ++i)
#pragma unroll
                for (int j = 0; j < 8; ++j)
                    acc[i][j] = fmaf(a[i], b[j], acc[i][j]);
        }
        __syncthreads();
    }

    // Epilogue
    if (scatter) {
        // out index: [(b*H + h)*S + s]*D + d  with m=b*S+s, n=h*D+d
#pragma unroll
        for (int i = 0; i < 8; ++i) {
            int m  = m0 + ty * 8 + i;
            int b_ = m >> 11;            // /2048
            int s  = m & 2047;
#pragma unroll
            for (int jg = 0; jg < 2; ++jg) {
                int n = n0 + tx * 8 + jg * 4;
                int h = n >> 6;
                int d = n & 63;
                float4 v = make_float4(acc[i][jg * 4 + 0], acc[i][jg * 4 + 1],
                                       acc[i][jg * 4 + 2], acc[i][jg * 4 + 3]);
                *(float4*)&out[(((b_ * HH + h) * SS) + s) * DD + d] = v;
            }
        }
    } else {
#pragma unroll
        for (int i = 0; i < 8; ++i) {
            int m = m0 + ty * 8 + i;
            int n = n0 + tx * 8;
            *(float4*)&out[m * EE + n]     = make_float4(acc[i][0], acc[i][1], acc[i][2], acc[i][3]);
            *(float4*)&out[m * EE + n + 4] = make_float4(acc[i][4], acc[i][5], acc[i][6], acc[i][7]);
        }
    }
}

// ---------------------------------------------------------------------------
// Flash attention: per (b,h), softmax(Q K^T / sqrt(D)) V with online softmax.
// BM=64 query rows per block, BN=32 key rows per tile, D=64.
// 256 threads: GEMM1 micro-tile 4x2, GEMM2 micro-tile 4x4.
// Writes ctx to [B,S,E] layout.
// ---------------------------------------------------------------------------
__global__ __launch_bounds__(256) void attn_kernel()
{
    __shared__ float Qt[64][68];   // [d][r], scaled by 1/sqrt(D)
    __shared__ float Kt[64][36];   // [d][j]
    __shared__ float Vs[32][68];   // [j][d]
    __shared__ float Sb[64][36];   // [r][j] scores -> probabilities
    __shared__ float rm[64], rl[64], rf[64];

    const int tid = threadIdx.x;
    const int ty  = tid >> 4;      // 0..15
    const int tx  = tid & 15;      // 0..15
    const int bh  = blockIdx.y;    // 0..63
    const int s0  = blockIdx.x * 64;
    const int b_  = bh >> 4;
    const int h   = bh & 15;

    const int base = bh * SS * DD; // offset into [B,H,S,D]
    const float scale = 0.125f;    // 1/sqrt(64)

    if (tid < 64) { rm[tid] = -1e30f; rl[tid] = 0.0f; }

    // Load Q tile transposed (scaled)
    for (int idx = tid; idx < 64 * 16; idx += 256) {
        int r  = idx >> 4;
        int dg = (idx & 15) * 4;
        float4 v = *(const float4*)&g_q[base + (s0 + r) * DD + dg];
        Qt[dg + 0][r] = v.x * scale;
        Qt[dg + 1][r] = v.y * scale;
        Qt[dg + 2][r] = v.z * scale;
        Qt[dg + 3][r] = v.w * scale;
    }

    float accv[4][4];
#pragma unroll
    for (int i = 0; i < 4; ++i)
#pragma unroll
        for (int j = 0; j < 4; ++j) accv[i][j] = 0.0f;

    __syncthreads();

    for (int t = 0; t < SS / 32; ++t) {
        const int j0 = t * 32;

        // Load K tile transposed (scalar), V tile natural (vectorized)
        for (int idx = tid; idx < 32 * 64; idx += 256) {
            int j = idx >> 6;
            int d = idx & 63;
            Kt[d][j] = g_k[base + (j0 + j) * DD + d];
        }
        for (int idx = tid; idx < 32 * 16; idx += 256) {
            int j  = idx >> 4;
            int dg = (idx & 15) * 4;
            *(float4*)&Vs[j][dg] = *(const float4*)&g_v[base + (j0 + j) * DD + dg];
        }
        __syncthreads();

        // GEMM1: S[r][j] = sum_d Qt[d][r] * Kt[d][j]
        float sc[4][2];
#pragma unroll
        for (int i = 0; i < 4; ++i) { sc[i][0] = 0.0f; sc[i][1] = 0.0f; }
#pragma unroll 8
        for (int d = 0; d < 64; ++d) {
            float4 a = *(const float4*)&Qt[d][ty * 4];
            float2 bv = *(const float2*)&Kt[d][tx * 2];
            sc[0][0] = fmaf(a.x, bv.x, sc[0][0]); sc[0][1] = fmaf(a.x, bv.y, sc[0][1]);
            sc[1][0] = fmaf(a.y, bv.x, sc[1][0]); sc[1][1] = fmaf(a.y, bv.y, sc[1][1]);
            sc[2][0] = fmaf(a.z, bv.x, sc[2][0]); sc[2][1] = fmaf(a.z, bv.y, sc[2][1]);
            sc[3][0] = fmaf(a.w, bv.x, sc[3][0]); sc[3][1] = fmaf(a.w, bv.y, sc[3][1]);
        }
#pragma unroll
        for (int i = 0; i < 4; ++i) {
            Sb[ty * 4 + i][tx * 2 + 0] = sc[i][0];
            Sb[ty * 4 + i][tx * 2 + 1] = sc[i][1];
        }
        __syncthreads();

        // Online softmax, one thread per query row
        if (tid < 64) {
            int r = tid;
            float mt = -1e30f;
#pragma unroll 8
            for (int j = 0; j < 32; ++j) mt = fmaxf(mt, Sb[r][j]);
            float newm = fmaxf(rm[r], mt);
            float f = __expf(rm[r] - newm);
            float sum = 0.0f;
#pragma unroll 8
            for (int j = 0; j < 32; ++j) {
                float p = __expf(Sb[r][j] - newm);
                Sb[r][j] = p;
                sum += p;
            }
            rl[r] = rl[r] * f + sum;
            rm[r] = newm;
            rf[r] = f;
        }
        __syncthreads();

        // Rescale accumulators, then GEMM2: acc[r][d] += P[r][j] * V[j][d]
        {
            float f0 = rf[ty * 4 + 0], f1 = rf[ty * 4 + 1];
            float f2 = rf[ty * 4 + 2], f3 = rf[ty * 4 + 3];
#pragma unroll
            for (int k = 0; k < 4; ++k) {
                accv[0][k] *= f0; accv[1][k] *= f1;
                accv[2][k] *= f2; accv[3][k] *= f3;
            }
        }
#pragma unroll 4
        for (int j = 0; j < 32; ++j) {
            float4 v = *(const float4*)&Vs[j][tx * 4];
            float p0 = Sb[ty * 4 + 0][j];
            float p1 = Sb[ty * 4 + 1][j];
            float p2 = Sb[ty * 4 + 2][j];
            float p3 = Sb[ty * 4 + 3][j];
            accv[0][0] = fmaf(p0, v.x, accv[0][0]); accv[0][1] = fmaf(p0, v.y, accv[0][1]);
            accv[0][2] = fmaf(p0, v.z, accv[0][2]); accv[0][3] = fmaf(p0, v.w, accv[0][3]);
            accv[1][0] = fmaf(p1, v.x, accv[1][0]); accv[1][1] = fmaf(p1, v.y, accv[1][1]);
            accv[1][2] = fmaf(p1, v.z, accv[1][2]); accv[1][3] = fmaf(p1, v.w, accv[1][3]);
            accv[2][0] = fmaf(p2, v.x, accv[2][0]); accv[2][1] = fmaf(p2, v.y, accv[2][1]);
            accv[2][2] = fmaf(p2, v.z, accv[2][2]); accv[2][3] = fmaf(p2, v.w, accv[2][3]);
            accv[3][0] = fmaf(p3, v.x, accv[3][0]); accv[3][1] = fmaf(p3, v.y, accv[3][1]);
            accv[3][2] = fmaf(p3, v.z, accv[3][2]); accv[3][3] = fmaf(p3, v.w, accv[3][3]);
        }
        __syncthreads();
    }

    // Final normalize and write ctx [B,S,E] with E index = h*64 + d
#pragma unroll
    for (int i = 0; i < 4; ++i) {
        int r = ty * 4 + i;
        float invl = 1.0f / rl[r];
        float4 v = make_float4(accv[i][0] * invl, accv[i][1] * invl,
                               accv[i][2] * invl, accv[i][3] * invl);
        *(float4*)&g_ctx[(b_ * SS + s0 + r) * EE + h * DD + tx * 4] = v;
    }
}

// ---------------------------------------------------------------------------
extern "C" void kernel_launch(void* const* d_in, const int* in_sizes, int n_in,
                              void* d_out, int out_size)
{
    const float* query = (const float*)d_in[0];
    const float* key   = (const float*)d_in[1];
    const float* value = (const float*)d_in[2];
    const float* Wq    = (const float*)d_in[3];
    const float* Wk    = (const float*)d_in[4];
    const float* Wv    = (const float*)d_in[5];
    const float* Wo    = (const float*)d_in[6];

    float *pq, *pk, *pv, *pctx;
    cudaGetSymbolAddress((void**)&pq,   g_q);
    cudaGetSymbolAddress((void**)&pk,   g_k);
    cudaGetSymbolAddress((void**)&pv,   g_v);
    cudaGetSymbolAddress((void**)&pctx, g_ctx);

    dim3 gp(EE / 128, MM / 128);   // (8, 64)
    proj_gemm<<<gp, 256>>>(query, Wq, pq, 1);
    proj_gemm<<<gp, 256>>>(key,   Wk, pk, 1);
    proj_gemm<<<gp, 256>>>(value, Wv, pv, 1);

    attn_kernel<<<dim3(SS / 64, BB * HH), 256>>>();   // (32, 64)

    proj_gemm<<<gp, 256>>>(pctx, Wo, (float*)d_out, 0);
}

// round 4
// speedup vs baseline: 1.2425x; 1.2425x over previous
#include <cuda_runtime.h>
#include <cuda_bf16.h>
#include <cstdint>

// Problem constants
#define BB   4
#define SS   2048
#define EE   1024
#define HH   16
#define DD   64
#define MM   (BB * SS)          // 8192 rows for projections

// Scratch (device globals: allocation-free per harness rules)
__device__ float g_q[BB * HH * SS * DD];   // [B,H,S,D]
__device__ float g_k[BB * HH * SS * DD];
__device__ float g_v[BB * HH * SS * DD];
__device__ float g_ctx[MM * EE];           // [B,S,E]

// ---------------------------------------------------------------------------
// bf16 m16n8k16 MMA (arch-neutral PTX; compiles to HMMA on sm_103)
// ---------------------------------------------------------------------------
__device__ __forceinline__ void mma16816(float* d, const uint32_t* a, const uint32_t* b) {
    asm volatile(
        "mma.sync.aligned.m16n8k16.row.col.f32.bf16.bf16.f32 "
        "{%0,%1,%2,%3}, {%4,%5,%6,%7}, {%8,%9}, {%0,%1,%2,%3};"
        : "+f"(d[0]), "+f"(d[1]), "+f"(d[2]), "+f"(d[3])
        : "r"(a[0]), "r"(a[1]), "r"(a[2]), "r"(a[3]), "r"(b[0]), "r"(b[1]));
}

// ---------------------------------------------------------------------------
// Tensor-core projection GEMM with fused fp32->bf16(hi,lo) split.
// out[m,n] = sum_k A[m,k] * W[n,k]   (x @ W^T), fp32-accurate via 3-term split.
// A: [8192,1024] fp32, W: [1024,1024] fp32.
// Tile 128x128, BK=32. 256 threads = 8 warps, warp tile 64x32 (wm 0..1, wn 0..3).
// smem rows padded to 40 bf16 (80B) -> conflict-free fragment LDS.
// scatter=1 -> write [B,H,S,D]; scatter=0 -> row-major [m,n].
// ---------------------------------------------------------------------------
#define LDP 40   // padded smem row length in bf16

__global__ __launch_bounds__(256) void gemm_mma(
    const float* __restrict__ A,
    const float* __restrict__ W,
    float* __restrict__ out,
    int scatter)
{
    __shared__ __nv_bfloat16 sAh[128][LDP];
    __shared__ __nv_bfloat16 sAl[128][LDP];
    __shared__ __nv_bfloat16 sWh[128][LDP];
    __shared__ __nv_bfloat16 sWl[128][LDP];

    const int tid  = threadIdx.x;
    const int warp = tid >> 5;
    const int lane = tid & 31;
    const int gid  = lane >> 2;   // groupID 0..7
    const int tq   = lane & 3;    // quad    0..3

    const int m0 = blockIdx.y * 128;
    const int n0 = blockIdx.x * 128;

    const int wm = warp & 1;      // 2 m-blocks of 64
    const int wn = warp >> 1;     // 4 n-blocks of 32
    const int mbase = wm * 64;
    const int nbase = wn * 32;

    // Loader assignment: 2 threads per row, 16 consecutive k each.
    const int lrow = tid >> 1;           // 0..127
    const int lkh  = (tid & 1) * 16;     // 0 or 16

    const float* pa = A + (size_t)(m0 + lrow) * EE + lkh;
    const float* pw = W + (size_t)(n0 + lrow) * EE + lkh;

    float4 ra[4], rw[4];
#pragma unroll
    for (int q = 0; q < 4; ++q) { ra[q] = *(const float4*)(pa + q * 4); rw[q] = *(const float4*)(pw + q * 4); }

    float acc[4][4][4];
#pragma unroll
    for (int mt = 0; mt < 4; ++mt)
#pragma unroll
        for (int nt = 0; nt < 4; ++nt)
#pragma unroll
            for (int r = 0; r < 4; ++r) acc[mt][nt][r] = 0.0f;

    for (int it = 0; it < 32; ++it) {
        // ---- convert regs -> bf16 hi/lo, store to smem ----
        __nv_bfloat16 ahb[16], alb[16], whb[16], wlb[16];
#pragma unroll
        for (int q = 0; q < 4; ++q) {
            const float* fa = (const float*)&ra[q];
            const float* fw = (const float*)&rw[q];
#pragma unroll
            for (int e = 0; e < 4; ++e) {
                float xa = fa[e];
                __nv_bfloat16 ha = __float2bfloat16(xa);
                ahb[q * 4 + e] = ha;
                alb[q * 4 + e] = __float2bfloat16(xa - __bfloat162float(ha));
                float xw = fw[e];
                __nv_bfloat16 hw = __float2bfloat16(xw);
                whb[q * 4 + e] = hw;
                wlb[q * 4 + e] = __float2bfloat16(xw - __bfloat162float(hw));
            }
        }
        *(uint4*)&sAh[lrow][lkh]     = *(uint4*)&ahb[0];
        *(uint4*)&sAh[lrow][lkh + 8] = *(uint4*)&ahb[8];
        *(uint4*)&sAl[lrow][lkh]     = *(uint4*)&alb[0];
        *(uint4*)&sAl[lrow][lkh + 8] = *(uint4*)&alb[8];
        *(uint4*)&sWh[lrow][lkh]     = *(uint4*)&whb[0];
        *(uint4*)&sWh[lrow][lkh + 8] = *(uint4*)&whb[8];
        *(uint4*)&sWl[lrow][lkh]     = *(uint4*)&wlb[0];
        *(uint4*)&sWl[lrow][lkh + 8] = *(uint4*)&wlb[8];
        __syncthreads();

        // ---- prefetch next fp32 tile (overlaps with MMA below) ----
        if (it < 31) {
            pa += 32; pw += 32;
#pragma unroll
            for (int q = 0; q < 4; ++q) { ra[q] = *(const float4*)(pa + q * 4); rw[q] = *(const float4*)(pw + q * 4); }
        }

        // ---- compute: 2 k16 steps, 3-term split ----
#pragma unroll
        for (int ks = 0; ks < 2; ++ks) {
            const int k = ks * 16;
            uint32_t ah[4][4], al[4][4];
#pragma unroll
            for (int mt = 0; mt < 4; ++mt) {
                const int m = mbase + mt * 16 + gid;
                ah[mt][0] = *(const uint32_t*)&sAh[m][k + 2 * tq];
                ah[mt][1] = *(const uint32_t*)&sAh[m + 8][k + 2 * tq];
                ah[mt][2] = *(const uint32_t*)&sAh[m][k + 8 + 2 * tq];
                ah[mt][3] = *(const uint32_t*)&sAh[m + 8][k + 8 + 2 * tq];
                al[mt][0] = *(const uint32_t*)&sAl[m][k + 2 * tq];
                al[mt][1] = *(const uint32_t*)&sAl[m + 8][k + 2 * tq];
                al[mt][2] = *(const uint32_t*)&sAl[m][k + 8 + 2 * tq];
                al[mt][3] = *(const uint32_t*)&sAl[m + 8][k + 8 + 2 * tq];
            }
            uint32_t bh[4][2], bl[4][2];
#pragma unroll
            for (int nt = 0; nt < 4; ++nt) {
                const int n = nbase + nt * 8 + gid;
                bh[nt][0] = *(const uint32_t*)&sWh[n][k + 2 * tq];
                bh[nt][1] = *(const uint32_t*)&sWh[n][k + 8 + 2 * tq];
                bl[nt][0] = *(const uint32_t*)&sWl[n][k + 2 * tq];
                bl[nt][1] = *(const uint32_t*)&sWl[n][k + 8 + 2 * tq];
            }
#pragma unroll
            for (int mt = 0; mt < 4; ++mt)
#pragma unroll
                for (int nt = 0; nt < 4; ++nt) {
                    mma16816(acc[mt][nt], ah[mt], bh[nt]);   // hi*hi
                    mma16816(acc[mt][nt], ah[mt], bl[nt]);   // hi*lo
                    mma16816(acc[mt][nt], al[mt], bh[nt]);   // lo*hi
                }
        }
        __syncthreads();
    }

    // ---- epilogue ----
#pragma unroll
    for (int mt = 0; mt < 4; ++mt) {
        const int r0 = m0 + mbase + mt * 16 + gid;
        const int r1 = r0 + 8;
#pragma unroll
        for (int nt = 0; nt < 4; ++nt) {
            const int n = n0 + nbase + nt * 8 + 2 * tq;
            float2 v01 = make_float2(acc[mt][nt][0], acc[mt][nt][1]);
            float2 v23 = make_float2(acc[mt][nt][2], acc[mt][nt][3]);
            if (scatter) {
                const int h = n >> 6;
                const int d = n & 63;
                {
                    const int b_ = r0 >> 11, s = r0 & 2047;
                    *(float2*)&out[(((size_t)(b_ * HH + h) * SS) + s) * DD + d] = v01;
                }
                {
                    const int b_ = r1 >> 11, s = r1 & 2047;
                    *(float2*)&out[(((size_t)(b_ * HH + h) * SS) + s) * DD + d] = v23;
                }
            } else {
                *(float2*)&out[(size_t)r0 * EE + n] = v01;
                *(float2*)&out[(size_t)r1 * EE + n] = v23;
            }
        }
    }
}

// ---------------------------------------------------------------------------
// Flash attention (fp32, validated in R2): per (b,h), softmax(Q K^T / 8) V.
// ---------------------------------------------------------------------------
__global__ __launch_bounds__(256) void attn_kernel()
{
    __shared__ float Qt[64][68];
    __shared__ float Kt[64][36];
    __shared__ float Vs[32][68];
    __shared__ float Sb[64][36];
    __shared__ float rm[64], rl[64], rf[64];

    const int tid = threadIdx.x;
    const int ty  = tid >> 4;
    const int tx  = tid & 15;
    const int bh  = blockIdx.y;
    const int s0  = blockIdx.x * 64;
    const int b_  = bh >> 4;
    const int h   = bh & 15;

    const int base = bh * SS * DD;
    const float scale = 0.125f;

    if (tid < 64) { rm[tid] = -1e30f; rl[tid] = 0.0f; }

    for (int idx = tid; idx < 64 * 16; idx += 256) {
        int r  = idx >> 4;
        int dg = (idx & 15) * 4;
        float4 v = *(const float4*)&g_q[base + (s0 + r) * DD + dg];
        Qt[dg + 0][r] = v.x * scale;
        Qt[dg + 1][r] = v.y * scale;
        Qt[dg + 2][r] = v.z * scale;
        Qt[dg + 3][r] = v.w * scale;
    }

    float accv[4][4];
#pragma unroll
    for (int i = 0; i < 4; ++i)
#pragma unroll
        for (int j = 0; j < 4; ++j) accv[i][j] = 0.0f;

    __syncthreads();

    for (int t = 0; t < SS / 32; ++t) {
        const int j0 = t * 32;

        for (int idx = tid; idx < 32 * 64; idx += 256) {
            int j = idx >> 6;
            int d = idx & 63;
            Kt[d][j] = g_k[base + (j0 + j) * DD + d];
        }
        for (int idx = tid; idx < 32 * 16; idx += 256) {
            int j  = idx >> 4;
            int dg = (idx & 15) * 4;
            *(float4*)&Vs[j][dg] = *(const float4*)&g_v[base + (j0 + j) * DD + dg];
        }
        __syncthreads();

        float sc[4][2];
#pragma unroll
        for (int i = 0; i < 4; ++i) { sc[i][0] = 0.0f; sc[i][1] = 0.0f; }
#pragma unroll 8
        for (int d = 0; d < 64; ++d) {
            float4 a = *(const float4*)&Qt[d][ty * 4];
            float2 bv = *(const float2*)&Kt[d][tx * 2];
            sc[0][0] = fmaf(a.x, bv.x, sc[0][0]); sc[0][1] = fmaf(a.x, bv.y, sc[0][1]);
            sc[1][0] = fmaf(a.y, bv.x, sc[1][0]); sc[1][1] = fmaf(a.y, bv.y, sc[1][1]);
            sc[2][0] = fmaf(a.z, bv.x, sc[2][0]); sc[2][1] = fmaf(a.z, bv.y, sc[2][1]);
            sc[3][0] = fmaf(a.w, bv.x, sc[3][0]); sc[3][1] = fmaf(a.w, bv.y, sc[3][1]);
        }
#pragma unroll
        for (int i = 0; i < 4; ++i) {
            Sb[ty * 4 + i][tx * 2 + 0] = sc[i][0];
            Sb[ty * 4 + i][tx * 2 + 1] = sc[i][1];
        }
        __syncthreads();

        if (tid < 64) {
            int r = tid;
            float mt = -1e30f;
#pragma unroll 8
            for (int j = 0; j < 32; ++j) mt = fmaxf(mt, Sb[r][j]);
            float newm = fmaxf(rm[r], mt);
            float f = __expf(rm[r] - newm);
            float sum = 0.0f;
#pragma unroll 8
            for (int j = 0; j < 32; ++j) {
                float p = __expf(Sb[r][j] - newm);
                Sb[r][j] = p;
                sum += p;
            }
            rl[r] = rl[r] * f + sum;
            rm[r] = newm;
            rf[r] = f;
        }
        __syncthreads();

        {
            float f0 = rf[ty * 4 + 0], f1 = rf[ty * 4 + 1];
            float f2 = rf[ty * 4 + 2], f3 = rf[ty * 4 + 3];
#pragma unroll
            for (int k = 0; k < 4; ++k) {
                accv[0][k] *= f0; accv[1][k] *= f1;
                accv[2][k] *= f2; accv[3][k] *= f3;
            }
        }
#pragma unroll 4
        for (int j = 0; j < 32; ++j) {
            float4 v = *(const float4*)&Vs[j][tx * 4];
            float p0 = Sb[ty * 4 + 0][j];
            float p1 = Sb[ty * 4 + 1][j];
            float p2 = Sb[ty * 4 + 2][j];
            float p3 = Sb[ty * 4 + 3][j];
            accv[0][0] = fmaf(p0, v.x, accv[0][0]); accv[0][1] = fmaf(p0, v.y, accv[0][1]);
            accv[0][2] = fmaf(p0, v.z, accv[0][2]); accv[0][3] = fmaf(p0, v.w, accv[0][3]);
            accv[1][0] = fmaf(p1, v.x, accv[1][0]); accv[1][1] = fmaf(p1, v.y, accv[1][1]);
            accv[1][2] = fmaf(p1, v.z, accv[1][2]); accv[1][3] = fmaf(p1, v.w, accv[1][3]);
            accv[2][0] = fmaf(p2, v.x, accv[2][0]); accv[2][1] = fmaf(p2, v.y, accv[2][1]);
            accv[2][2] = fmaf(p2, v.z, accv[2][2]); accv[2][3] = fmaf(p2, v.w, accv[2][3]);
            accv[3][0] = fmaf(p3, v.x, accv[3][0]); accv[3][1] = fmaf(p3, v.y, accv[3][1]);
            accv[3][2] = fmaf(p3, v.z, accv[3][2]); accv[3][3] = fmaf(p3, v.w, accv[3][3]);
        }
        __syncthreads();
    }

#pragma unroll
    for (int i = 0; i < 4; ++i) {
        int r = ty * 4 + i;
        float invl = 1.0f / rl[r];
        float4 v = make_float4(accv[i][0] * invl, accv[i][1] * invl,
                               accv[i][2] * invl, accv[i][3] * invl);
        *(float4*)&g_ctx[(b_ * SS + s0 + r) * EE + h * DD + tx * 4] = v;
    }
}

// ---------------------------------------------------------------------------
extern "C" void kernel_launch(void* const* d_in, const int* in_sizes, int n_in,
                              void* d_out, int out_size)
{
    const float* query = (const float*)d_in[0];
    const float* key   = (const float*)d_in[1];
    const float* value = (const float*)d_in[2];
    const float* Wq    = (const float*)d_in[3];
    const float* Wk    = (const float*)d_in[4];
    const float* Wv    = (const float*)d_in[5];
    const float* Wo    = (const float*)d_in[6];

    float *pq, *pk, *pv, *pctx;
    cudaGetSymbolAddress((void**)&pq,   g_q);
    cudaGetSymbolAddress((void**)&pk,   g_k);
    cudaGetSymbolAddress((void**)&pv,   g_v);
    cudaGetSymbolAddress((void**)&pctx, g_ctx);

    dim3 gg(EE / 128, MM / 128);   // (8, 64)

    gemm_mma<<<gg, 256>>>(query, Wq, pq, 1);
    gemm_mma<<<gg, 256>>>(key,   Wk, pk, 1);
    gemm_mma<<<gg, 256>>>(value, Wv, pv, 1);

    attn_kernel<<<dim3(SS / 64, BB * HH), 256>>>();

    gemm_mma<<<gg, 256>>>(pctx, Wo, (float*)d_out, 0);
}

// round 5
// speedup vs baseline: 1.3828x; 1.1129x over previous
#include <cuda_runtime.h>
#include <cuda_bf16.h>
#include <cstdint>

// Problem constants
#define BB   4
#define SS   2048
#define EE   1024
#define HH   16
#define DD   64
#define MM   (BB * SS)          // 8192 rows for projections

// Scratch (device globals: allocation-free per harness rules)
__device__ float g_q[BB * HH * SS * DD];   // [B,H,S,D]
__device__ float g_k[BB * HH * SS * DD];
__device__ float g_v[BB * HH * SS * DD];
__device__ float g_ctx[MM * EE];           // [B,S,E]
__device__ __nv_bfloat16 g_ahi[MM * EE];
__device__ __nv_bfloat16 g_alo[MM * EE];
__device__ __nv_bfloat16 g_whi[EE * EE];
__device__ __nv_bfloat16 g_wlo[EE * EE];

// ---------------------------------------------------------------------------
// PTX helpers (arch-neutral: sm_80-era, safe for compute_103)
// ---------------------------------------------------------------------------
__device__ __forceinline__ uint32_t smem_u32(const void* p) {
    uint32_t a;
    asm("{ .reg .u64 t; cvta.to.shared.u64 t, %1; cvt.u32.u64 %0, t; }" : "=r"(a) : "l"(p));
    return a;
}
__device__ __forceinline__ void cp_async16(uint32_t dst, const void* src) {
    asm volatile("cp.async.cg.shared.global [%0], [%1], 16;" :: "r"(dst), "l"(src));
}
__device__ __forceinline__ void cp_commit() {
    asm volatile("cp.async.commit_group;" ::: "memory");
}
template <int N>
__device__ __forceinline__ void cp_wait() {
    asm volatile("cp.async.wait_group %0;" :: "n"(N) : "memory");
}
__device__ __forceinline__ void ldmatrix_x4(uint32_t* r, uint32_t addr) {
    asm volatile("ldmatrix.sync.aligned.m8n8.x4.shared.b16 {%0,%1,%2,%3}, [%4];"
                 : "=r"(r[0]), "=r"(r[1]), "=r"(r[2]), "=r"(r[3]) : "r"(addr));
}
__device__ __forceinline__ void mma16816(float* d, const uint32_t* a, const uint32_t* b) {
    asm volatile(
        "mma.sync.aligned.m16n8k16.row.col.f32.bf16.bf16.f32 "
        "{%0,%1,%2,%3}, {%4,%5,%6,%7}, {%8,%9}, {%0,%1,%2,%3};"
        : "+f"(d[0]), "+f"(d[1]), "+f"(d[2]), "+f"(d[3])
        : "r"(a[0]), "r"(a[1]), "r"(a[2]), "r"(a[3]), "r"(b[0]), "r"(b[1]));
}

// ---------------------------------------------------------------------------
// Split conversion: x (fp32) -> hi = bf16(x), lo = bf16(x - hi). 4 elems/thread.
// ---------------------------------------------------------------------------
__global__ __launch_bounds__(256) void split_bf16(
    const float* __restrict__ x,
    __nv_bfloat16* __restrict__ hi,
    __nv_bfloat16* __restrict__ lo)
{
    int i = (blockIdx.x * 256 + threadIdx.x) * 4;
    float4 v = *(const float4*)(x + i);
    __nv_bfloat16 h0 = __float2bfloat16(v.x);
    __nv_bfloat16 h1 = __float2bfloat16(v.y);
    __nv_bfloat16 h2 = __float2bfloat16(v.z);
    __nv_bfloat16 h3 = __float2bfloat16(v.w);
    __nv_bfloat16 l0 = __float2bfloat16(v.x - __bfloat162float(h0));
    __nv_bfloat16 l1 = __float2bfloat16(v.y - __bfloat162float(h1));
    __nv_bfloat16 l2 = __float2bfloat16(v.z - __bfloat162float(h2));
    __nv_bfloat16 l3 = __float2bfloat16(v.w - __bfloat162float(h3));
    __nv_bfloat162* hp = (__nv_bfloat162*)(hi + i);
    __nv_bfloat162* lp = (__nv_bfloat162*)(lo + i);
    hp[0] = __nv_bfloat162(h0, h1); hp[1] = __nv_bfloat162(h2, h3);
    lp[0] = __nv_bfloat162(l0, l1); lp[1] = __nv_bfloat162(l2, l3);
}

// ---------------------------------------------------------------------------
// 3-term bf16 HMMA GEMM: out[m,n] = sum_k A[m,k]*W[n,k] (fp32-accurate).
// Pre-split bf16 inputs. Tile 128x128, BK=32, cp.async double buffer,
// ldmatrix fragments. 8 warps, warp tile 64x32.
// smem row pitch LDP=40 bf16 (80B): conflict-free ldmatrix (8 rows hit
// disjoint 4-bank groups: 80B stride -> bank offsets 0,20,8,28,16,4,24,12).
// ---------------------------------------------------------------------------
#define LDP 40
#define ARR_B   (128 * LDP * 2)          // 10240 bytes per array
#define STAGE_B (4 * ARR_B)              // Ah, Al, Wh, Wl = 40960
#define GEMM_SMEM (2 * STAGE_B)          // 81920

__global__ __launch_bounds__(256) void gemm_bf16(
    const __nv_bfloat16* __restrict__ Ahi, const __nv_bfloat16* __restrict__ Alo,
    const __nv_bfloat16* __restrict__ Whi, const __nv_bfloat16* __restrict__ Wlo,
    float* __restrict__ out, int scatter)
{
    extern __shared__ char smem[];
    const uint32_t sbase = smem_u32(smem);

    const int tid  = threadIdx.x;
    const int warp = tid >> 5;
    const int lane = tid & 31;
    const int gid  = lane >> 2;
    const int tq   = lane & 3;

    const int m0 = blockIdx.y * 128;
    const int n0 = blockIdx.x * 128;
    const int mbase = (warp & 1) * 64;    // 2 m-blocks of 64
    const int nbase = (warp >> 1) * 32;   // 4 n-blocks of 32

    // per-lane ldmatrix byte offsets (within array, before mt/nt/k adjust)
    const uint32_t a_byte = (uint32_t)(((lane & 7) + ((lane >> 3) & 1) * 8) * LDP
                                       + ((lane >> 4) & 1) * 8) * 2;
    const uint32_t b_byte = (uint32_t)(((lane & 7) + ((lane >> 4) & 1) * 8) * LDP) * 2
                            + ((lane >> 3) & 1) * 16;

    // loader: 2048 16B chunks per stage; thread handles 8
    // chunk idx: arr = c>>9 (0:Ah 1:Al 2:Wh 3:Wl), row=(c&511)>>2, seg=c&3
    const __nv_bfloat16* gsrc[4] = { Ahi, Alo, Whi, Wlo };

    auto load_stage = [&](int stg, int k0) {
        const uint32_t dst0 = sbase + stg * STAGE_B;
#pragma unroll
        for (int q = 0; q < 8; ++q) {
            int c   = tid + q * 256;
            int arr = c >> 9;
            int row = (c & 511) >> 2;
            int seg = c & 3;
            int grow = (arr < 2 ? m0 : n0) + row;
            const __nv_bfloat16* src = gsrc[arr] + (size_t)grow * EE + k0 + seg * 8;
            uint32_t dst = dst0 + arr * ARR_B + (row * LDP + seg * 8) * 2;
            cp_async16(dst, src);
        }
    };

    float acc[4][4][4];
#pragma unroll
    for (int mt = 0; mt < 4; ++mt)
#pragma unroll
        for (int nt = 0; nt < 4; ++nt)
#pragma unroll
            for (int r = 0; r < 4; ++r) acc[mt][nt][r] = 0.0f;

    load_stage(0, 0);
    cp_commit();

    for (int it = 0; it < 32; ++it) {
        const int stg = it & 1;
        if (it < 31) { load_stage(stg ^ 1, (it + 1) * 32); cp_commit(); cp_wait<1>(); }
        else         { cp_wait<0>(); }
        __syncthreads();

        const uint32_t s0 = sbase + stg * STAGE_B;
#pragma unroll
        for (int ks = 0; ks < 2; ++ks) {
            const uint32_t koff = ks * 32;   // 16 bf16 = 32 bytes
            uint32_t ah[4][4], al[4][4], bh[4][2], bl[4][2];
#pragma unroll
            for (int mt = 0; mt < 4; ++mt) {
                uint32_t aoff = (uint32_t)((mbase + mt * 16) * LDP * 2) + koff + a_byte;
                ldmatrix_x4(ah[mt], s0 + aoff);                // Ah
                ldmatrix_x4(al[mt], s0 + ARR_B + aoff);        // Al
            }
#pragma unroll
            for (int np = 0; np < 2; ++np) {
                uint32_t boff = (uint32_t)((nbase + np * 16) * LDP * 2) + koff + b_byte;
                uint32_t rb[4];
                ldmatrix_x4(rb, s0 + 2 * ARR_B + boff);        // Wh
                bh[2 * np][0] = rb[0]; bh[2 * np][1] = rb[1];
                bh[2 * np + 1][0] = rb[2]; bh[2 * np + 1][1] = rb[3];
                ldmatrix_x4(rb, s0 + 3 * ARR_B + boff);        // Wl
                bl[2 * np][0] = rb[0]; bl[2 * np][1] = rb[1];
                bl[2 * np + 1][0] = rb[2]; bl[2 * np + 1][1] = rb[3];
            }
#pragma unroll
            for (int mt = 0; mt < 4; ++mt)
#pragma unroll
                for (int nt = 0; nt < 4; ++nt) {
                    mma16816(acc[mt][nt], ah[mt], bh[nt]);   // hi*hi
                    mma16816(acc[mt][nt], ah[mt], bl[nt]);   // hi*lo
                    mma16816(acc[mt][nt], al[mt], bh[nt]);   // lo*hi
                }
        }
        __syncthreads();
    }

    // epilogue: thread(gid,tq) of warp holds rows mt*16+gid(+8), cols nt*8+2tq(+1)
#pragma unroll
    for (int mt = 0; mt < 4; ++mt) {
        const int r0 = m0 + mbase + mt * 16 + gid;
        const int r1 = r0 + 8;
#pragma unroll
        for (int nt = 0; nt < 4; ++nt) {
            const int n = n0 + nbase + nt * 8 + 2 * tq;
            float2 v01 = make_float2(acc[mt][nt][0], acc[mt][nt][1]);
            float2 v23 = make_float2(acc[mt][nt][2], acc[mt][nt][3]);
            if (scatter) {
                const int h = n >> 6;
                const int d = n & 63;
                { const int b_ = r0 >> 11, s = r0 & 2047;
                  *(float2*)&out[(((size_t)(b_ * HH + h) * SS) + s) * DD + d] = v01; }
                { const int b_ = r1 >> 11, s = r1 & 2047;
                  *(float2*)&out[(((size_t)(b_ * HH + h) * SS) + s) * DD + d] = v23; }
            } else {
                *(float2*)&out[(size_t)r0 * EE + n] = v01;
                *(float2*)&out[(size_t)r1 * EE + n] = v23;
            }
        }
    }
}

// ---------------------------------------------------------------------------
// Flash attention (fp32, validated): per (b,h), softmax(Q K^T / 8) V.
// ---------------------------------------------------------------------------
__global__ __launch_bounds__(256) void attn_kernel()
{
    __shared__ float Qt[64][68];
    __shared__ float Kt[64][36];
    __shared__ float Vs[32][68];
    __shared__ float Sb[64][36];
    __shared__ float rm[64], rl[64], rf[64];

    const int tid = threadIdx.x;
    const int ty  = tid >> 4;
    const int tx  = tid & 15;
    const int bh  = blockIdx.y;
    const int s0  = blockIdx.x * 64;
    const int b_  = bh >> 4;
    const int h   = bh & 15;

    const int base = bh * SS * DD;
    const float scale = 0.125f;

    if (tid < 64) { rm[tid] = -1e30f; rl[tid] = 0.0f; }

    for (int idx = tid; idx < 64 * 16; idx += 256) {
        int r  = idx >> 4;
        int dg = (idx & 15) * 4;
        float4 v = *(const float4*)&g_q[base + (s0 + r) * DD + dg];
        Qt[dg + 0][r] = v.x * scale;
        Qt[dg + 1][r] = v.y * scale;
        Qt[dg + 2][r] = v.z * scale;
        Qt[dg + 3][r] = v.w * scale;
    }

    float accv[4][4];
#pragma unroll
    for (int i = 0; i < 4; ++i)
#pragma unroll
        for (int j = 0; j < 4; ++j) accv[i][j] = 0.0f;

    __syncthreads();

    for (int t = 0; t < SS / 32; ++t) {
        const int j0 = t * 32;

        for (int idx = tid; idx < 32 * 64; idx += 256) {
            int j = idx >> 6;
            int d = idx & 63;
            Kt[d][j] = g_k[base + (j0 + j) * DD + d];
        }
        for (int idx = tid; idx < 32 * 16; idx += 256) {
            int j  = idx >> 4;
            int dg = (idx & 15) * 4;
            *(float4*)&Vs[j][dg] = *(const float4*)&g_v[base + (j0 + j) * DD + dg];
        }
        __syncthreads();

        float sc[4][2];
#pragma unroll
        for (int i = 0; i < 4; ++i) { sc[i][0] = 0.0f; sc[i][1] = 0.0f; }
#pragma unroll 8
        for (int d = 0; d < 64; ++d) {
            float4 a = *(const float4*)&Qt[d][ty * 4];
            float2 bv = *(const float2*)&Kt[d][tx * 2];
            sc[0][0] = fmaf(a.x, bv.x, sc[0][0]); sc[0][1] = fmaf(a.x, bv.y, sc[0][1]);
            sc[1][0] = fmaf(a.y, bv.x, sc[1][0]); sc[1][1] = fmaf(a.y, bv.y, sc[1][1]);
            sc[2][0] = fmaf(a.z, bv.x, sc[2][0]); sc[2][1] = fmaf(a.z, bv.y, sc[2][1]);
            sc[3][0] = fmaf(a.w, bv.x, sc[3][0]); sc[3][1] = fmaf(a.w, bv.y, sc[3][1]);
        }
#pragma unroll
        for (int i = 0; i < 4; ++i) {
            Sb[ty * 4 + i][tx * 2 + 0] = sc[i][0];
            Sb[ty * 4 + i][tx * 2 + 1] = sc[i][1];
        }
        __syncthreads();

        if (tid < 64) {
            int r = tid;
            float mt = -1e30f;
#pragma unroll 8
            for (int j = 0; j < 32; ++j) mt = fmaxf(mt, Sb[r][j]);
            float newm = fmaxf(rm[r], mt);
            float f = __expf(rm[r] - newm);
            float sum = 0.0f;
#pragma unroll 8
            for (int j = 0; j < 32; ++j) {
                float p = __expf(Sb[r][j] - newm);
                Sb[r][j] = p;
                sum += p;
            }
            rl[r] = rl[r] * f + sum;
            rm[r] = newm;
            rf[r] = f;
        }
        __syncthreads();

        {
            float f0 = rf[ty * 4 + 0], f1 = rf[ty * 4 + 1];
            float f2 = rf[ty * 4 + 2], f3 = rf[ty * 4 + 3];
#pragma unroll
            for (int k = 0; k < 4; ++k) {
                accv[0][k] *= f0; accv[1][k] *= f1;
                accv[2][k] *= f2; accv[3][k] *= f3;
            }
        }
#pragma unroll 4
        for (int j = 0; j < 32; ++j) {
            float4 v = *(const float4*)&Vs[j][tx * 4];
            float p0 = Sb[ty * 4 + 0][j];
            float p1 = Sb[ty * 4 + 1][j];
            float p2 = Sb[ty * 4 + 2][j];
            float p3 = Sb[ty * 4 + 3][j];
            accv[0][0] = fmaf(p0, v.x, accv[0][0]); accv[0][1] = fmaf(p0, v.y, accv[0][1]);
            accv[0][2] = fmaf(p0, v.z, accv[0][2]); accv[0][3] = fmaf(p0, v.w, accv[0][3]);
            accv[1][0] = fmaf(p1, v.x, accv[1][0]); accv[1][1] = fmaf(p1, v.y, accv[1][1]);
            accv[1][2] = fmaf(p1, v.z, accv[1][2]); accv[1][3] = fmaf(p1, v.w, accv[1][3]);
            accv[2][0] = fmaf(p2, v.x, accv[2][0]); accv[2][1] = fmaf(p2, v.y, accv[2][1]);
            accv[2][2] = fmaf(p2, v.z, accv[2][2]); accv[2][3] = fmaf(p2, v.w, accv[2][3]);
            accv[3][0] = fmaf(p3, v.x, accv[3][0]); accv[3][1] = fmaf(p3, v.y, accv[3][1]);
            accv[3][2] = fmaf(p3, v.z, accv[3][2]); accv[3][3] = fmaf(p3, v.w, accv[3][3]);
        }
        __syncthreads();
    }

#pragma unroll
    for (int i = 0; i < 4; ++i) {
        int r = ty * 4 + i;
        float invl = 1.0f / rl[r];
        float4 v = make_float4(accv[i][0] * invl, accv[i][1] * invl,
                               accv[i][2] * invl, accv[i][3] * invl);
        *(float4*)&g_ctx[(b_ * SS + s0 + r) * EE + h * DD + tx * 4] = v;
    }
}

// ---------------------------------------------------------------------------
extern "C" void kernel_launch(void* const* d_in, const int* in_sizes, int n_in,
                              void* d_out, int out_size)
{
    const float* query = (const float*)d_in[0];
    const float* key   = (const float*)d_in[1];
    const float* value = (const float*)d_in[2];
    const float* Wq    = (const float*)d_in[3];
    const float* Wk    = (const float*)d_in[4];
    const float* Wv    = (const float*)d_in[5];
    const float* Wo    = (const float*)d_in[6];

    float *pq, *pk, *pv, *pctx;
    __nv_bfloat16 *ahi, *alo, *whi, *wlo;
    cudaGetSymbolAddress((void**)&pq,   g_q);
    cudaGetSymbolAddress((void**)&pk,   g_k);
    cudaGetSymbolAddress((void**)&pv,   g_v);
    cudaGetSymbolAddress((void**)&pctx, g_ctx);
    cudaGetSymbolAddress((void**)&ahi,  g_ahi);
    cudaGetSymbolAddress((void**)&alo,  g_alo);
    cudaGetSymbolAddress((void**)&whi,  g_whi);
    cudaGetSymbolAddress((void**)&wlo,  g_wlo);

    cudaFuncSetAttribute(gemm_bf16, cudaFuncAttributeMaxDynamicSharedMemorySize, GEMM_SMEM);

    const int nA = MM * EE;   // 8M
    const int nW = EE * EE;   // 1M
    dim3 gg(EE / 128, MM / 128);   // (8, 64)

    // Q projection
    split_bf16<<<nA / 1024, 256>>>(query, ahi, alo);
    split_bf16<<<nW / 1024, 256>>>(Wq, whi, wlo);
    gemm_bf16<<<gg, 256, GEMM_SMEM>>>(ahi, alo, whi, wlo, pq, 1);
    // K projection
    split_bf16<<<nA / 1024, 256>>>(key, ahi, alo);
    split_bf16<<<nW / 1024, 256>>>(Wk, whi, wlo);
    gemm_bf16<<<gg, 256, GEMM_SMEM>>>(ahi, alo, whi, wlo, pk, 1);
    // V projection
    split_bf16<<<nA / 1024, 256>>>(value, ahi, alo);
    split_bf16<<<nW / 1024, 256>>>(Wv, whi, wlo);
    gemm_bf16<<<gg, 256, GEMM_SMEM>>>(ahi, alo, whi, wlo, pv, 1);

    // Attention
    attn_kernel<<<dim3(SS / 64, BB * HH), 256>>>();

    // Output projection
    split_bf16<<<nA / 1024, 256>>>(pctx, ahi, alo);
    split_bf16<<<nW / 1024, 256>>>(Wo, whi, wlo);
    gemm_bf16<<<gg, 256, GEMM_SMEM>>>(ahi, alo, whi, wlo, (float*)d_out, 0);
}

// round 9
// speedup vs baseline: 3.1210x; 2.2570x over previous
#include <cuda_runtime.h>
#include <cuda_bf16.h>
#include <cstdint>

// Problem constants
#define BB   4
#define SS   2048
#define EE   1024
#define HH   16
#define DD   64
#define MM   (BB * SS)

// Scratch (device globals)
__device__ __nv_bfloat16 g_ahi[MM * EE];
__device__ __nv_bfloat16 g_alo[MM * EE];
__device__ __nv_bfloat16 g_whi[EE * EE];
__device__ __nv_bfloat16 g_wlo[EE * EE];
__device__ __nv_bfloat16 g_qh[BB * HH * SS * DD];
__device__ __nv_bfloat16 g_ql[BB * HH * SS * DD];
__device__ __nv_bfloat16 g_kh[BB * HH * SS * DD];
__device__ __nv_bfloat16 g_kl[BB * HH * SS * DD];
__device__ __nv_bfloat16 g_vh[BB * HH * SS * DD];
__device__ __nv_bfloat16 g_vl[BB * HH * SS * DD];

// ---------------------------------------------------------------------------
// PTX helpers (arch-neutral)
// ---------------------------------------------------------------------------
__device__ __forceinline__ uint32_t smem_u32(const void* p) {
    uint32_t a;
    asm("{ .reg .u64 t; cvta.to.shared.u64 t, %1; cvt.u32.u64 %0, t; }" : "=r"(a) : "l"(p));
    return a;
}
__device__ __forceinline__ void cp_async16(uint32_t dst, const void* src) {
    asm volatile("cp.async.cg.shared.global [%0], [%1], 16;" :: "r"(dst), "l"(src));
}
__device__ __forceinline__ void cp_commit() {
    asm volatile("cp.async.commit_group;" ::: "memory");
}
template <int N>
__device__ __forceinline__ void cp_wait() {
    asm volatile("cp.async.wait_group %0;" :: "n"(N) : "memory");
}
__device__ __forceinline__ void ldmatrix_x4(uint32_t* r, uint32_t addr) {
    asm volatile("ldmatrix.sync.aligned.m8n8.x4.shared.b16 {%0,%1,%2,%3}, [%4];"
                 : "=r"(r[0]), "=r"(r[1]), "=r"(r[2]), "=r"(r[3]) : "r"(addr));
}
__device__ __forceinline__ void ldmatrix_x4_t(uint32_t* r, uint32_t addr) {
    asm volatile("ldmatrix.sync.aligned.m8n8.x4.trans.shared.b16 {%0,%1,%2,%3}, [%4];"
                 : "=r"(r[0]), "=r"(r[1]), "=r"(r[2]), "=r"(r[3]) : "r"(addr));
}
__device__ __forceinline__ void mma16816(float* d, const uint32_t* a, const uint32_t* b) {
    asm volatile(
        "mma.sync.aligned.m16n8k16.row.col.f32.bf16.bf16.f32 "
        "{%0,%1,%2,%3}, {%4,%5,%6,%7}, {%8,%9}, {%0,%1,%2,%3};"
        : "+f"(d[0]), "+f"(d[1]), "+f"(d[2]), "+f"(d[3])
        : "r"(a[0]), "r"(a[1]), "r"(a[2]), "r"(a[3]), "r"(b[0]), "r"(b[1]));
}
__device__ __forceinline__ float ex2(float x) {
    float y; asm("ex2.approx.f32 %0, %1;" : "=f"(y) : "f"(x)); return y;
}
// pack (x,y) -> bf16x2 hi {lo=x,hi=y}; residual lo pack in lo_pack
__device__ __forceinline__ uint32_t pack_split(float x, float y, uint32_t& lo_pack) {
    uint32_t h;
    asm("cvt.rn.bf16x2.f32 %0, %1, %2;" : "=r"(h) : "f"(y), "f"(x));
    float hx = __uint_as_float(h << 16);
    float hy = __uint_as_float(h & 0xFFFF0000u);
    uint32_t l;
    asm("cvt.rn.bf16x2.f32 %0, %1, %2;" : "=r"(l) : "f"(y - hy), "f"(x - hx));
    lo_pack = l;
    return h;
}

// ---------------------------------------------------------------------------
// Split conversion: x (fp32) -> hi, lo (bf16). 4 elems/thread.
// ---------------------------------------------------------------------------
__global__ __launch_bounds__(256) void split_bf16(
    const float* __restrict__ x,
    __nv_bfloat16* __restrict__ hi,
    __nv_bfloat16* __restrict__ lo)
{
    int i = (blockIdx.x * 256 + threadIdx.x) * 4;
    float4 v = *(const float4*)(x + i);
    uint32_t l0, l1;
    uint32_t h0 = pack_split(v.x, v.y, l0);
    uint32_t h1 = pack_split(v.z, v.w, l1);
    *(uint2*)(hi + i) = make_uint2(h0, h1);
    *(uint2*)(lo + i) = make_uint2(l0, l1);
}

// ---------------------------------------------------------------------------
// 3-term bf16 HMMA GEMM (projections): out = A @ W^T.
// scatter=1: write split bf16 hi/lo to [B,H,S,D] arrays, scaled.
// scatter=0: write fp32 row-major to outF.
// ---------------------------------------------------------------------------
#define LDP 40
#define ARR_B   (128 * LDP * 2)
#define STAGE_B (4 * ARR_B)
#define GEMM_SMEM (2 * STAGE_B)

__global__ __launch_bounds__(256) void gemm_bf16(
    const __nv_bfloat16* __restrict__ Ahi, const __nv_bfloat16* __restrict__ Alo,
    const __nv_bfloat16* __restrict__ Whi, const __nv_bfloat16* __restrict__ Wlo,
    float* __restrict__ outF,
    __nv_bfloat16* __restrict__ outHi, __nv_bfloat16* __restrict__ outLo,
    int scatter, float scale)
{
    extern __shared__ char smem[];
    const uint32_t sbase = smem_u32(smem);

    const int tid  = threadIdx.x;
    const int warp = tid >> 5;
    const int lane = tid & 31;
    const int gid  = lane >> 2;
    const int tq   = lane & 3;

    const int m0 = blockIdx.y * 128;
    const int n0 = blockIdx.x * 128;
    const int mbase = (warp & 1) * 64;
    const int nbase = (warp >> 1) * 32;

    const uint32_t a_byte = (uint32_t)(((lane & 7) + ((lane >> 3) & 1) * 8) * LDP
                                       + ((lane >> 4) & 1) * 8) * 2;
    const uint32_t b_byte = (uint32_t)(((lane & 7) + ((lane >> 4) & 1) * 8) * LDP) * 2
                            + ((lane >> 3) & 1) * 16;

    const __nv_bfloat16* gsrc[4] = { Ahi, Alo, Whi, Wlo };

    auto load_stage = [&](int stg, int k0) {
        const uint32_t dst0 = sbase + stg * STAGE_B;
#pragma unroll
        for (int q = 0; q < 8; ++q) {
            int c   = tid + q * 256;
            int arr = c >> 9;
            int row = (c & 511) >> 2;
            int seg = c & 3;
            int grow = (arr < 2 ? m0 : n0) + row;
            const __nv_bfloat16* src = gsrc[arr] + (size_t)grow * EE + k0 + seg * 8;
            cp_async16(dst0 + arr * ARR_B + (row * LDP + seg * 8) * 2, src);
        }
    };

    float acc[4][4][4];
#pragma unroll
    for (int mt = 0; mt < 4; ++mt)
#pragma unroll
        for (int nt = 0; nt < 4; ++nt)
#pragma unroll
            for (int r = 0; r < 4; ++r) acc[mt][nt][r] = 0.0f;

    load_stage(0, 0);
    cp_commit();

    for (int it = 0; it < 32; ++it) {
        const int stg = it & 1;
        if (it < 31) { load_stage(stg ^ 1, (it + 1) * 32); cp_commit(); cp_wait<1>(); }
        else         { cp_wait<0>(); }
        __syncthreads();

        const uint32_t s0 = sbase + stg * STAGE_B;
#pragma unroll
        for (int ks = 0; ks < 2; ++ks) {
            const uint32_t koff = ks * 32;
            uint32_t ah[4][4], al[4][4], bh[4][2], bl[4][2];
#pragma unroll
            for (int mt = 0; mt < 4; ++mt) {
                uint32_t aoff = (uint32_t)((mbase + mt * 16) * LDP * 2) + koff + a_byte;
                ldmatrix_x4(ah[mt], s0 + aoff);
                ldmatrix_x4(al[mt], s0 + ARR_B + aoff);
            }
#pragma unroll
            for (int np = 0; np < 2; ++np) {
                uint32_t boff = (uint32_t)((nbase + np * 16) * LDP * 2) + koff + b_byte;
                uint32_t rb[4];
                ldmatrix_x4(rb, s0 + 2 * ARR_B + boff);
                bh[2 * np][0] = rb[0]; bh[2 * np][1] = rb[1];
                bh[2 * np + 1][0] = rb[2]; bh[2 * np + 1][1] = rb[3];
                ldmatrix_x4(rb, s0 + 3 * ARR_B + boff);
                bl[2 * np][0] = rb[0]; bl[2 * np][1] = rb[1];
                bl[2 * np + 1][0] = rb[2]; bl[2 * np + 1][1] = rb[3];
            }
#pragma unroll
            for (int mt = 0; mt < 4; ++mt)
#pragma unroll
                for (int nt = 0; nt < 4; ++nt) {
                    mma16816(acc[mt][nt], ah[mt], bh[nt]);
                    mma16816(acc[mt][nt], ah[mt], bl[nt]);
                    mma16816(acc[mt][nt], al[mt], bh[nt]);
                }
        }
        __syncthreads();
    }

#pragma unroll
    for (int mt = 0; mt < 4; ++mt) {
        const int r0 = m0 + mbase + mt * 16 + gid;
        const int r1 = r0 + 8;
#pragma unroll
        for (int nt = 0; nt < 4; ++nt) {
            const int n = n0 + nbase + nt * 8 + 2 * tq;
            if (scatter) {
                const int h = n >> 6;
                const int d = n & 63;
                {
                    const int b_ = r0 >> 11, s = r0 & 2047;
                    size_t idx = (((size_t)(b_ * HH + h) * SS) + s) * DD + d;
                    uint32_t lo, hi = pack_split(acc[mt][nt][0] * scale, acc[mt][nt][1] * scale, lo);
                    *(uint32_t*)(outHi + idx) = hi;
                    *(uint32_t*)(outLo + idx) = lo;
                }
                {
                    const int b_ = r1 >> 11, s = r1 & 2047;
                    size_t idx = (((size_t)(b_ * HH + h) * SS) + s) * DD + d;
                    uint32_t lo, hi = pack_split(acc[mt][nt][2] * scale, acc[mt][nt][3] * scale, lo);
                    *(uint32_t*)(outHi + idx) = hi;
                    *(uint32_t*)(outLo + idx) = lo;
                }
            } else {
                *(float2*)&outF[(size_t)r0 * EE + n] = make_float2(acc[mt][nt][0], acc[mt][nt][1]);
                *(float2*)&outF[(size_t)r1 * EE + n] = make_float2(acc[mt][nt][2], acc[mt][nt][3]);
            }
        }
    }
}

// ---------------------------------------------------------------------------
// HMMA flash attention. BM=128 (8 warps x 16 rows), BN=64 keys/tile, D=64.
// Q/K/V pre-split bf16 hi/lo; Q pre-scaled by 0.125*log2(e).
// 3-term splits on both QK^T and P*V. Triple-buffered cp.async K/V stages.
// Writes ctx split (bf16 hi/lo) to g_ahi/g_alo in [B,S,E] layout.
// ---------------------------------------------------------------------------
#define AP   72                      // smem pitch (bf16)
#define APB  144                     // pitch bytes
#define QB   (128 * APB)             // 18432 per Q array
#define KVA  (64 * APB)              // 9216 per K/V array
#define STGB (4 * KVA)               // 36864 per stage (Kh,Kl,Vh,Vl)
#define ATT_SMEM (2 * QB + 3 * STGB) // 147456

__global__ __launch_bounds__(256) void attn_mma(
    __nv_bfloat16* __restrict__ chi, __nv_bfloat16* __restrict__ clo)
{
    extern __shared__ char smem[];
    const uint32_t sbase = smem_u32(smem);

    const int tid  = threadIdx.x;
    const int warp = tid >> 5;
    const int lane = tid & 31;
    const int gid  = lane >> 2;
    const int tq   = lane & 3;

    const int bh = blockIdx.y;
    const int b_ = bh >> 4;
    const int h  = bh & 15;
    const int s0 = blockIdx.x * 128;
    const size_t kvoff = (size_t)bh * SS * DD;

    const __nv_bfloat16* kv_src[4] = { g_kh + kvoff, g_kl + kvoff, g_vh + kvoff, g_vl + kvoff };

    // ---- Q tile load (once) ----
#pragma unroll
    for (int q = 0; q < 8; ++q) {
        int c = tid + q * 256;
        int arr = c >> 10;
        int row = (c >> 3) & 127;
        int seg = c & 7;
        const __nv_bfloat16* src = (arr ? g_ql : g_qh) + kvoff + (size_t)(s0 + row) * DD + seg * 8;
        cp_async16(sbase + arr * QB + row * APB + seg * 16, src);
    }
    cp_commit();

    auto load_kv = [&](int t, int st) {
        const int j0 = t * 64;
        const uint32_t sb = sbase + 2 * QB + st * STGB;
#pragma unroll
        for (int q = 0; q < 8; ++q) {
            int c = tid + q * 256;
            int arr = c >> 9;
            int row = (c >> 3) & 63;
            int seg = c & 7;
            cp_async16(sb + arr * KVA + row * APB + seg * 16,
                       kv_src[arr] + (size_t)(j0 + row) * DD + seg * 8);
        }
        cp_commit();
    };

    load_kv(0, 0);
    load_kv(1, 1);

    cp_wait<2>();
    __syncthreads();

    // ---- Q fragments to registers ----
    const int wr0 = warp * 16;
    uint32_t qhf[4][4], qlf[4][4];
#pragma unroll
    for (int ks = 0; ks < 4; ++ks) {
        uint32_t addr = sbase + (wr0 + (lane & 15)) * APB + ks * 32 + ((lane >> 4) & 1) * 16;
        ldmatrix_x4(qhf[ks], addr);
        ldmatrix_x4(qlf[ks], addr + QB);
    }

    float of[8][4];
#pragma unroll
    for (int nb = 0; nb < 8; ++nb)
#pragma unroll
        for (int r = 0; r < 4; ++r) of[nb][r] = 0.0f;
    float m0 = -1e30f, m1 = -1e30f, l0 = 0.0f, l1 = 0.0f;

    for (int t = 0; t < 32; ++t) {
        if (t + 1 < 32) cp_wait<1>(); else cp_wait<0>();
        __syncthreads();
        if (t + 2 < 32) load_kv(t + 2, (t + 2) % 3);

        const uint32_t stb = sbase + 2 * QB + (t % 3) * STGB;

        // ---- QK^T -> sf (3-term) ----
        float sf[8][4];
#pragma unroll
        for (int nb = 0; nb < 8; ++nb)
#pragma unroll
            for (int r = 0; r < 4; ++r) sf[nb][r] = 0.0f;

#pragma unroll
        for (int ks = 0; ks < 4; ++ks) {
            uint32_t kh[8][2], kl[8][2];
#pragma unroll
            for (int np = 0; np < 4; ++np) {
                uint32_t addr = stb + (np * 16 + (lane & 15)) * APB + ks * 32 + ((lane >> 4) & 1) * 16;
                uint32_t r[4];
                ldmatrix_x4(r, addr);
                kh[2 * np][0] = r[0]; kh[2 * np + 1][0] = r[1];
                kh[2 * np][1] = r[2]; kh[2 * np + 1][1] = r[3];
                ldmatrix_x4(r, addr + KVA);
                kl[2 * np][0] = r[0]; kl[2 * np + 1][0] = r[1];
                kl[2 * np][1] = r[2]; kl[2 * np + 1][1] = r[3];
            }
#pragma unroll
            for (int nb = 0; nb < 8; ++nb) {
                mma16816(sf[nb], qhf[ks], kh[nb]);
                mma16816(sf[nb], qhf[ks], kl[nb]);
                mma16816(sf[nb], qlf[ks], kh[nb]);
            }
        }

        // ---- online softmax (scores already in log2 domain) ----
        float mx0 = -1e30f, mx1 = -1e30f;
#pragma unroll
        for (int nb = 0; nb < 8; ++nb) {
            mx0 = fmaxf(mx0, fmaxf(sf[nb][0], sf[nb][1]));
            mx1 = fmaxf(mx1, fmaxf(sf[nb][2], sf[nb][3]));
        }
        mx0 = fmaxf(mx0, __shfl_xor_sync(0xffffffffu, mx0, 1));
        mx0 = fmaxf(mx0, __shfl_xor_sync(0xffffffffu, mx0, 2));
        mx1 = fmaxf(mx1, __shfl_xor_sync(0xffffffffu, mx1, 1));
        mx1 = fmaxf(mx1, __shfl_xor_sync(0xffffffffu, mx1, 2));
        const float m0n = fmaxf(m0, mx0);
        const float m1n = fmaxf(m1, mx1);
        const float f0 = ex2(m0 - m0n);
        const float f1 = ex2(m1 - m1n);
        m0 = m0n; m1 = m1n;

        float sum0 = 0.0f, sum1 = 0.0f;
        uint32_t pEh[8], pEl[8], pOh[8], pOl[8];
#pragma unroll
        for (int nb = 0; nb < 8; ++nb) {
            float p0 = ex2(sf[nb][0] - m0n);
            float p1 = ex2(sf[nb][1] - m0n);
            float p2 = ex2(sf[nb][2] - m1n);
            float p3 = ex2(sf[nb][3] - m1n);
            sum0 += p0 + p1; sum1 += p2 + p3;
            pEh[nb] = pack_split(p0, p1, pEl[nb]);
            pOh[nb] = pack_split(p2, p3, pOl[nb]);
        }
        l0 = l0 * f0 + sum0;
        l1 = l1 * f1 + sum1;
#pragma unroll
        for (int nb = 0; nb < 8; ++nb) {
            of[nb][0] *= f0; of[nb][1] *= f0;
            of[nb][2] *= f1; of[nb][3] *= f1;
        }

        // ---- P*V (3-term) ----
#pragma unroll
        for (int ks = 0; ks < 4; ++ks) {
            uint32_t bvh[8][2], bvl[8][2];
#pragma unroll
            for (int np = 0; np < 4; ++np) {
                uint32_t addr = stb + 2 * KVA + (ks * 16 + (lane & 15)) * APB
                                + np * 32 + ((lane >> 4) & 1) * 16;
                uint32_t r[4];
                ldmatrix_x4_t(r, addr);
                bvh[2 * np][0] = r[0]; bvh[2 * np][1] = r[1];
                bvh[2 * np + 1][0] = r[2]; bvh[2 * np + 1][1] = r[3];
                ldmatrix_x4_t(r, addr + KVA);
                bvl[2 * np][0] = r[0]; bvl[2 * np][1] = r[1];
                bvl[2 * np + 1][0] = r[2]; bvl[2 * np + 1][1] = r[3];
            }
            uint32_t ah[4] = { pEh[2 * ks], pOh[2 * ks], pEh[2 * ks + 1], pOh[2 * ks + 1] };
            uint32_t al[4] = { pEl[2 * ks], pOl[2 * ks], pEl[2 * ks + 1], pOl[2 * ks + 1] };
#pragma unroll
            for (int nb = 0; nb < 8; ++nb) {
                mma16816(of[nb], ah, bvh[nb]);
                mma16816(of[nb], ah, bvl[nb]);
                mma16816(of[nb], al, bvh[nb]);
            }
        }
    }

    // ---- epilogue: normalize, split, write ctx [B,S,E] ----
    l0 += __shfl_xor_sync(0xffffffffu, l0, 1);
    l0 += __shfl_xor_sync(0xffffffffu, l0, 2);
    l1 += __shfl_xor_sync(0xffffffffu, l1, 1);
    l1 += __shfl_xor_sync(0xffffffffu, l1, 2);
    const float inv0 = 1.0f / l0;
    const float inv1 = 1.0f / l1;

    const int r0 = s0 + wr0 + gid;
    const int r1 = r0 + 8;
    const size_t base0 = ((size_t)(b_ * SS + r0)) * EE + h * DD;
    const size_t base1 = ((size_t)(b_ * SS + r1)) * EE + h * DD;
#pragma unroll
    for (int nb = 0; nb < 8; ++nb) {
        const int d = nb * 8 + 2 * tq;
        uint32_t lo, hi;
        hi = pack_split(of[nb][0] * inv0, of[nb][1] * inv0, lo);
        *(uint32_t*)(chi + base0 + d) = hi;
        *(uint32_t*)(clo + base0 + d) = lo;
        hi = pack_split(of[nb][2] * inv1, of[nb][3] * inv1, lo);
        *(uint32_t*)(chi + base1 + d) = hi;
        *(uint32_t*)(clo + base1 + d) = lo;
    }
}

// ---------------------------------------------------------------------------
extern "C" void kernel_launch(void* const* d_in, const int* in_sizes, int n_in,
                              void* d_out, int out_size)
{
    const float* query = (const float*)d_in[0];
    const float* key   = (const float*)d_in[1];
    const float* value = (const float*)d_in[2];
    const float* Wq    = (const float*)d_in[3];
    const float* Wk    = (const float*)d_in[4];
    const float* Wv    = (const float*)d_in[5];
    const float* Wo    = (const float*)d_in[6];

    __nv_bfloat16 *ahi, *alo, *whi, *wlo, *qh, *ql, *kh, *kl, *vh, *vl;
    cudaGetSymbolAddress((void**)&ahi, g_ahi);
    cudaGetSymbolAddress((void**)&alo, g_alo);
    cudaGetSymbolAddress((void**)&whi, g_whi);
    cudaGetSymbolAddress((void**)&wlo, g_wlo);
    cudaGetSymbolAddress((void**)&qh,  g_qh);
    cudaGetSymbolAddress((void**)&ql,  g_ql);
    cudaGetSymbolAddress((void**)&kh,  g_kh);
    cudaGetSymbolAddress((void**)&kl,  g_kl);
    cudaGetSymbolAddress((void**)&vh,  g_vh);
    cudaGetSymbolAddress((void**)&vl,  g_vl);

    cudaFuncSetAttribute(gemm_bf16, cudaFuncAttributeMaxDynamicSharedMemorySize, GEMM_SMEM);
    cudaFuncSetAttribute(attn_mma,  cudaFuncAttributeMaxDynamicSharedMemorySize, ATT_SMEM);

    const int nA = MM * EE;
    const int nW = EE * EE;
    dim3 gg(EE / 128, MM / 128);
    const float qscale = 0.125f * 1.44269504088896f;   // fold 1/sqrt(D) and log2(e)

    // Q projection -> split q (scaled)
    split_bf16<<<nA / 1024, 256>>>(query, ahi, alo);
    split_bf16<<<nW / 1024, 256>>>(Wq, whi, wlo);
    gemm_bf16<<<gg, 256, GEMM_SMEM>>>(ahi, alo, whi, wlo, nullptr, qh, ql, 1, qscale);
    // K projection
    split_bf16<<<nA / 1024, 256>>>(key, ahi, alo);
    split_bf16<<<nW / 1024, 256>>>(Wk, whi, wlo);
    gemm_bf16<<<gg, 256, GEMM_SMEM>>>(ahi, alo, whi, wlo, nullptr, kh, kl, 1, 1.0f);
    // V projection
    split_bf16<<<nA / 1024, 256>>>(value, ahi, alo);
    split_bf16<<<nW / 1024, 256>>>(Wv, whi, wlo);
    gemm_bf16<<<gg, 256, GEMM_SMEM>>>(ahi, alo, whi, wlo, nullptr, vh, vl, 1, 1.0f);

    // Attention (writes ctx split directly into ahi/alo)
    attn_mma<<<dim3(SS / 128, BB * HH), 256, ATT_SMEM>>>(ahi, alo);

    // Output projection
    split_bf16<<<nW / 1024, 256>>>(Wo, whi, wlo);
    gemm_bf16<<<gg, 256, GEMM_SMEM>>>(ahi, alo, whi, wlo, (float*)d_out, nullptr, nullptr, 0, 1.0f);
}